// round 14
// baseline (speedup 1.0000x reference)
#include <cuda_runtime.h>
#include <cstdint>
#include <cfloat>

// Problem constants
#define N_TOTAL   32768
#define DIM       256
#define KCODES    1024
#define NTILES    512         // 64-row tiles
#define THREADS   256
#define GRID_VQ   296         // 148 SMs * 2 CTAs (occupancy-2 persistent grid)
#define ZSTR      72          // zs row stride (floats) >= 64; 72 % 32 == 8
#define CAP       32
#define EPSF      6e-3f       // >= 2x worst-case bf16 screening score error

#define QOUT_ELEMS   (32 * DIM * 32 * 32)
#define LOSS_ELEMS   N_TOTAL

// smem word offsets
#define W_ZS      0           // 256*72 = 18432
#define W_ZA      18432       // 32 pair-rows * 72 = 2304 (bf16x2 z fragments)
#define W_WSB     20736       // 32 e-rows * 136 = 4352 (bf16x2 codebook slab)
#define W_ROWMIN  25088       // 64
#define W_COUNT   25152       // 64
#define W_ROWIDX  25216       // 64
#define W_TILE    25280       // 4
#define W_ZSQ     25284       // 64
#define W_CAND    25348       // 64*32 = 2048
#define SMEM_WORDS 27396      // 109584 bytes -> 2 CTAs/SM

__device__ float    g_wsq[KCODES];
__device__ uint32_t g_wpk[(DIM / 2) * KCODES];  // bf16x2 pairs (w[2e][c] lo, w[2e+1][c] hi)
__device__ float    g_wT[KCODES * DIM];         // transposed original w
__device__ int      g_tile_ctr;

__device__ __forceinline__ uint32_t pack_bf16x2(float lo, float hi) {
    uint32_t r;
    asm("cvt.rn.bf16x2.f32 %0, %1, %2;" : "=r"(r) : "f"(hi), "f"(lo));
    return r;
}
// m16n8k16 bf16 mma: D = A*B + D (fp32 accum)
__device__ __forceinline__ void mma_bf16(float* c, const uint32_t* a,
                                         uint32_t b0, uint32_t b1) {
    asm volatile(
        "mma.sync.aligned.m16n8k16.row.col.f32.bf16.bf16.f32 "
        "{%0,%1,%2,%3}, {%4,%5,%6,%7}, {%8,%9}, {%0,%1,%2,%3};"
        : "+f"(c[0]), "+f"(c[1]), "+f"(c[2]), "+f"(c[3])
        : "r"(a[0]), "r"(a[1]), "r"(a[2]), "r"(a[3]), "r"(b0), "r"(b1));
}

// ---------------------------------------------------------------------------
// wsq[k] = sum_d w[d][k]^2 ; also resets the tile counter (runs before vq)
__global__ void __launch_bounds__(256)
wsq_kernel(const float* __restrict__ w) {
    __shared__ float red[8][32];
    const int tx = threadIdx.x, ty = threadIdx.y;
    if (blockIdx.x == 0 && tx == 0 && ty == 0) g_tile_ctr = 0;
    const int k = blockIdx.x * 32 + tx;
    float s = 0.f;
#pragma unroll
    for (int i = 0; i < 32; i++) {
        float v = w[(size_t)(ty + 8 * i) * KCODES + k];
        s = __fadd_rn(s, __fmul_rn(v, v));
    }
    red[ty][tx] = s;
    __syncthreads();
    if (ty == 0) {
        float t = red[0][tx];
#pragma unroll
        for (int j = 1; j < 8; j++) t = __fadd_rn(t, red[j][tx]);
        g_wsq[k] = t;
    }
}

// w prep: g_wpk (bf16x2 d-pairs) + g_wT (transpose)
__global__ void __launch_bounds__(1024)
wprep_kernel(const float* __restrict__ w) {
    __shared__ float t[32][33];
    const int tx = threadIdx.x, ty = threadIdx.y;
    const int c0 = blockIdx.x * 32, d0 = blockIdx.y * 32;
    float v = w[(size_t)(d0 + ty) * KCODES + c0 + tx];
    t[ty][tx] = v;
    __syncthreads();
    g_wT[(size_t)(c0 + ty) * DIM + d0 + tx] = t[tx][ty];
    if (ty < 16) {
        const int e = (d0 >> 1) + ty;
        g_wpk[(size_t)e * KCODES + c0 + tx] = pack_bf16x2(t[2 * ty][tx], t[2 * ty + 1][tx]);
    }
}

// ---------------------------------------------------------------------------
// Persistent fused kernel: in-tile zsq + bf16 screening GEMM (64-d stages,
// register-prefetched W slabs) + conservative collect + exact fp32 rescue
// argmin + gather + q_st + losses.
// ---------------------------------------------------------------------------
__global__ void __launch_bounds__(THREADS, 2)
vq_kernel(const float* __restrict__ z, const float* __restrict__ w,
          float* __restrict__ qout, float* __restrict__ loss,
          float* __restrict__ commit, float* __restrict__ embed) {
    extern __shared__ float sm[];
    float*    zs      = sm + W_ZS;
    uint32_t* zA      = (uint32_t*)(sm + W_ZA);
    uint32_t* wsB     = (uint32_t*)(sm + W_WSB);
    int*      srowmin = (int*)(sm + W_ROWMIN);
    int*      scount  = (int*)(sm + W_COUNT);
    int*      srowidx = (int*)(sm + W_ROWIDX);
    int*      stile   = (int*)(sm + W_TILE);
    float*    szsq    = sm + W_ZSQ;
    int*      scand   = (int*)(sm + W_CAND);
    float*    part    = (float*)scand;          // alias: zsq-combine + epilogue

    const int tid  = threadIdx.x;
    const int warp = tid >> 5;
    const int lane = tid & 31;
    const int wr = (warp & 1) * 32;
    const int wc = (warp >> 1) * 32;
    const int lg = lane >> 2;
    const int lt = lane & 3;

    // W slab staging indices
    const int we0 = tid >> 5;          // 0..7
    const int wc16 = tid & 31;

    for (;;) {
        if (tid == 0) stile[0] = atomicAdd(&g_tile_ctr, 1);
        __syncthreads();
        const int tile = stile[0];
        if (tile >= NTILES) break;

        const int n0  = tile * 64;
        const int b   = n0 >> 10;
        const int hw0 = n0 & 1023;
        const float* zbase = z + ((size_t)(b * DIM) << 10) + hw0;

        // ---- load z tile (fp32, kept for rescue/epilogue) ----
        for (int i = tid; i < DIM * 16; i += THREADS) {
            int d = i >> 4, f = i & 15;
            *(float4*)(zs + d * ZSTR + f * 4) =
                *(const float4*)(zbase + ((size_t)d << 10) + f * 4);
        }

        // ---- preload W slab ss=0 into registers ----
        uint4 wpreA = *(const uint4*)(g_wpk + (size_t)we0 * KCODES + wc16 * 4);
        uint4 wpreB = *(const uint4*)(g_wpk + (size_t)(we0 + 8) * KCODES + wc16 * 4);
        uint4 wpreC = *(const uint4*)(g_wpk + (size_t)(we0 + 16) * KCODES + wc16 * 4);
        uint4 wpreD = *(const uint4*)(g_wpk + (size_t)(we0 + 24) * KCODES + wc16 * 4);

        __syncthreads();   // zs visible

        // ---- in-tile zsq (order argmin-irrelevant by grid-shift invariance) ----
        {
            const int r = tid & 63, dh = tid >> 6;
            float ps = 0.f;
#pragma unroll 8
            for (int d = dh; d < DIM; d += 4) {
                float v = zs[d * ZSTR + r];
                ps = __fmaf_rn(v, v, ps);
            }
            part[tid] = ps;
        }
        __syncthreads();
        if (tid < 64) {
            szsq[tid] = __fadd_rn(__fadd_rn(part[tid], part[64 + tid]),
                                  __fadd_rn(part[128 + tid], part[192 + tid]));
            srowmin[tid] = 0x7F7FFFFF;
            scount[tid] = 0;
        }
        __syncthreads();

        float tzsq[4];
#pragma unroll
        for (int mi = 0; mi < 2; mi++)
#pragma unroll
            for (int h = 0; h < 2; h++)
                tzsq[mi * 2 + h] = szsq[wr + mi * 16 + h * 8 + lg];

        // ---- screening: 8 k-tiles of 128 cols, 4 stages of 64 d each ----
        for (int kt = 0; kt < 8; kt++) {
            float acc[2][4][4];
#pragma unroll
            for (int mi = 0; mi < 2; mi++)
#pragma unroll
                for (int ni = 0; ni < 4; ni++)
#pragma unroll
                    for (int q = 0; q < 4; q++) acc[mi][ni][q] = 0.f;

            for (int st = 0; st < 4; st++) {
                const int ss = kt * 4 + st;
                __syncthreads();   // prior readers of zA/wsB done

                // store register-held slab ss into wsB (e-rows 0..31)
                *(uint4*)(wsB + we0 * 136 + wc16 * 4) = wpreA;
                *(uint4*)(wsB + (we0 + 8) * 136 + wc16 * 4) = wpreB;
                *(uint4*)(wsB + (we0 + 16) * 136 + wc16 * 4) = wpreC;
                *(uint4*)(wsB + (we0 + 24) * 136 + wc16 * 4) = wpreD;

                // stage zA: bf16x2 fragments for 64 d, 4 tasks/thread
#pragma unroll
                for (int j = 0; j < 4; j++) {
                    const int p = tid + j * 256;
                    const int r = p & 63, plt = (p >> 6) & 3, pcc = (p >> 8) & 3;
                    const int d0 = st * 64 + pcc * 16 + plt * 2;
                    float z0 = zs[d0 * ZSTR + r];
                    float z1 = zs[(d0 + 1) * ZSTR + r];
                    float z2 = zs[(d0 + 8) * ZSTR + r];
                    float z3 = zs[(d0 + 9) * ZSTR + r];
                    zA[(pcc * 4 + plt) * 72 + r]        = pack_bf16x2(z0, z1);
                    zA[(16 + pcc * 4 + plt) * 72 + r]   = pack_bf16x2(z2, z3);
                }
                __syncthreads();

                // prefetch slab ss+1 into registers (overlaps the MMAs)
                if (ss < 31) {
                    const int ssn = ss + 1;
                    const int nkt = ssn >> 2, nst = ssn & 3;
                    const size_t ebase = (size_t)(nst * 32) * KCODES
                                       + nkt * 128 + wc16 * 4;
                    wpreA = *(const uint4*)(g_wpk + ebase + (size_t)we0 * KCODES);
                    wpreB = *(const uint4*)(g_wpk + ebase + (size_t)(we0 + 8) * KCODES);
                    wpreC = *(const uint4*)(g_wpk + ebase + (size_t)(we0 + 16) * KCODES);
                    wpreD = *(const uint4*)(g_wpk + ebase + (size_t)(we0 + 24) * KCODES);
                }

                // compute: 4 k16-chunks, 2 mtiles x 4 ntiles
#pragma unroll
                for (int cc = 0; cc < 4; cc++) {
                    uint32_t a[2][4];
                    const int rlo = (cc * 4 + lt) * 72;
                    const int rhi = rlo + 16 * 72;
#pragma unroll
                    for (int mi = 0; mi < 2; mi++) {
                        const int r0 = wr + mi * 16 + lg;
                        a[mi][0] = zA[rlo + r0];
                        a[mi][1] = zA[rlo + r0 + 8];
                        a[mi][2] = zA[rhi + r0];
                        a[mi][3] = zA[rhi + r0 + 8];
                    }
#pragma unroll
                    for (int ni = 0; ni < 4; ni++) {
                        const int col = wc + ni * 8 + lg;
                        uint32_t b0 = wsB[(cc * 8 + lt) * 136 + col];
                        uint32_t b1 = wsB[(cc * 8 + lt + 4) * 136 + col];
                        mma_bf16(acc[0][ni], a[0], b0, b1);
                        mma_bf16(acc[1][ni], a[1], b0, b1);
                    }
                }
            }

            // pass 1: per-row screened running min
#pragma unroll
            for (int mi = 0; mi < 2; mi++)
#pragma unroll
                for (int h = 0; h < 2; h++) {
                    const int idx = mi * 2 + h;
                    float rm = FLT_MAX;
#pragma unroll
                    for (int ni = 0; ni < 4; ni++) {
                        const int col0 = kt * 128 + wc + ni * 8 + lt * 2;
                        float s0 = __fsub_rn(__fadd_rn(tzsq[idx], __ldg(&g_wsq[col0])),
                                             __fmul_rn(2.f, acc[mi][ni][h * 2]));
                        float s1 = __fsub_rn(__fadd_rn(tzsq[idx], __ldg(&g_wsq[col0 + 1])),
                                             __fmul_rn(2.f, acc[mi][ni][h * 2 + 1]));
                        rm = fminf(rm, fminf(s0, s1));
                    }
                    rm = fminf(rm, __shfl_xor_sync(0xffffffffu, rm, 1));
                    rm = fminf(rm, __shfl_xor_sync(0xffffffffu, rm, 2));
                    if (lt == 0)
                        atomicMin(&srowmin[wr + mi * 16 + h * 8 + lg],
                                  __float_as_int(rm));
                }
            __syncthreads();

            // pass 2: collect candidates <= running row min + EPS (conservative)
#pragma unroll
            for (int mi = 0; mi < 2; mi++)
#pragma unroll
                for (int h = 0; h < 2; h++) {
                    const int idx = mi * 2 + h;
                    const int row = wr + mi * 16 + h * 8 + lg;
                    const float thr = __int_as_float(srowmin[row]) + EPSF;
#pragma unroll
                    for (int ni = 0; ni < 4; ni++) {
                        const int col0 = kt * 128 + wc + ni * 8 + lt * 2;
                        float s0 = __fsub_rn(__fadd_rn(tzsq[idx], __ldg(&g_wsq[col0])),
                                             __fmul_rn(2.f, acc[mi][ni][h * 2]));
                        float s1 = __fsub_rn(__fadd_rn(tzsq[idx], __ldg(&g_wsq[col0 + 1])),
                                             __fmul_rn(2.f, acc[mi][ni][h * 2 + 1]));
                        if (s0 <= thr) {
                            int p = atomicAdd(&scount[row], 1);
                            if (p < CAP) scand[row * CAP + p] = col0;
                        }
                        if (s1 <= thr) {
                            int p = atomicAdd(&scount[row], 1);
                            if (p < CAP) scand[row * CAP + p] = col0 + 1;
                        }
                    }
                }
        }
        __syncthreads();

        // ---- exact rescue: 4 threads per row, fp32, exact bucketing ----
        {
            const int row = tid >> 2;
            const int t4  = tid & 3;
            const int cnt = scount[row];
            const float zsqr = szsq[row];
            float bv = FLT_MAX;
            int   bi = 0x7FFFFFFF;

            auto exact_score = [&](int c) -> float {
                const float4* wp = (const float4*)(g_wT + (size_t)c * DIM);
                float a0 = 0.f, a1 = 0.f, a2 = 0.f, a3 = 0.f;
#pragma unroll 8
                for (int dq = 0; dq < DIM / 4; dq++) {
                    float4 wv = __ldg(wp + dq);
                    const int d = dq * 4;
                    a0 = __fmaf_rn(zs[d * ZSTR + row], wv.x, a0);
                    a1 = __fmaf_rn(zs[(d + 1) * ZSTR + row], wv.y, a1);
                    a2 = __fmaf_rn(zs[(d + 2) * ZSTR + row], wv.z, a2);
                    a3 = __fmaf_rn(zs[(d + 3) * ZSTR + row], wv.w, a3);
                }
                float dot = __fadd_rn(__fadd_rn(__fadd_rn(a0, a1), a2), a3);
                return __fsub_rn(__fadd_rn(zsqr, __ldg(&g_wsq[c])),
                                 __fmul_rn(2.f, dot));
            };

            if (cnt <= CAP) {
                for (int i = t4; i < cnt; i += 4) {
                    int c = scand[row * CAP + i];
                    float s = exact_score(c);
                    if (s < bv || (s == bv && c < bi)) { bv = s; bi = c; }
                }
            } else {  // overflow: deterministic full scan
                for (int c = t4; c < KCODES; c += 4) {
                    float s = exact_score(c);
                    if (s < bv || (s == bv && c < bi)) { bv = s; bi = c; }
                }
            }
#pragma unroll
            for (int off = 1; off <= 2; off <<= 1) {
                float v2 = __shfl_xor_sync(0xffffffffu, bv, off);
                int   i2 = __shfl_xor_sync(0xffffffffu, bi, off);
                if (v2 < bv || (v2 == bv && i2 < bi)) { bv = v2; bi = i2; }
            }
            if (t4 == 0) srowidx[row] = bi;
        }
        __syncthreads();

        // ---- epilogue: gather code, q_st, losses ----
        const int r  = tid & 63;
        const int dh = tid >> 6;    // 0..3
        const int kstar = srowidx[r];
        const float* wrow = g_wT + (size_t)kstar * DIM;
        float* qb = qout + ((size_t)(b * DIM) << 10) + hw0;
        float partial = 0.f;
#pragma unroll 4
        for (int d = dh; d < DIM; d += 4) {
            float wv = __ldg(wrow + d);
            float zv = zs[d * ZSTR + r];
            float diff = __fsub_rn(wv, zv);
            partial = __fmaf_rn(diff, diff, partial);
            qb[((size_t)d << 10) + r] = __fadd_rn(zv, diff);  // z + (q - z)
        }
        __syncthreads();   // szsq reads done before part overwrite (alias safety)
        part[tid] = partial;
        __syncthreads();
        if (dh == 0) {
            float mse = __fmul_rn(
                __fadd_rn(__fadd_rn(part[r], part[64 + r]),
                          __fadd_rn(part[128 + r], part[192 + r])),
                1.0f / DIM);
            int n = n0 + r;
            commit[n] = mse;
            embed[n]  = mse;
            loss[n]   = __fadd_rn(__fmul_rn(0.25f, mse), mse);
        }
        __syncthreads();   // smem reuse barrier before next tile
    }
}

// ---------------------------------------------------------------------------
extern "C" void kernel_launch(void* const* d_in, const int* in_sizes, int n_in,
                              void* d_out, int out_size) {
    const float* z = (const float*)d_in[0];
    const float* w = (const float*)d_in[1];
    float* out    = (float*)d_out;
    float* qout   = out;
    float* loss   = out + QOUT_ELEMS;
    float* commit = loss + LOSS_ELEMS;
    float* embed  = commit + LOSS_ELEMS;

    wsq_kernel<<<KCODES / 32, dim3(32, 8)>>>(w);
    wprep_kernel<<<dim3(32, 8), dim3(32, 32)>>>(w);

    const size_t smem_bytes = SMEM_WORDS * sizeof(float);
    static bool attr_set = false;
    if (!attr_set) {
        cudaFuncSetAttribute(vq_kernel, cudaFuncAttributeMaxDynamicSharedMemorySize,
                             (int)smem_bytes);
        attr_set = true;
    }
    vq_kernel<<<GRID_VQ, THREADS, smem_bytes>>>(z, w, qout, loss, commit, embed);
}